// round 6
// baseline (speedup 1.0000x reference)
#include <cuda_runtime.h>
#include <math.h>

#define K_CTX 64
#define D_DIM 128
#define C_CAND 256
#define DS 200
#define EPS 1e-8f
#define M_HALF 32

// Scratch + sync (device globals; no allocation allowed)
__device__ __align__(16) float g_A[K_CTX * D_DIM];
__device__ __align__(16) float g_AM[K_CTX * D_DIM];
__device__ float g_rowpart[C_CAND][2][K_CTX];   // partial rowsum per m-half
__device__ float g_colsum[C_CAND][K_CTX];       // complete colsum (disjoint halves)
__device__ int   g_tick[C_CAND];                // per-candidate arrival ticket
__device__ int   g_count = 0;                   // AM rows produced
__device__ int   g_done  = 0;                   // blocks finished (reset)

// sB row stride 140 floats: 16B-aligned rows, LDS.128 conflict-free
// (per 8-lane phase, vec4 start words 12*l mod 32 cover all 32 banks)
#define SB_STRIDE 140
#define SB_VEC    (SB_STRIDE / 4)
#define SMEM_FLOATS (K_CTX * D_DIM + M_HALF * SB_STRIDE + 64 + 32 + 64 + 64 + 128 + 128 + 4)

// ---------------------------------------------------------------------------
// grid = 512: block (c = bid>>1, h = bid&1) handles candidate c, m-half h.
// Blocks 0..63 additionally produce AM row = bid.
// ---------------------------------------------------------------------------
__global__ __launch_bounds__(512, 4)
void cand_kernel(const float* __restrict__ table,
                 const float* __restrict__ str_t1,
                 const float* __restrict__ str_t2s,
                 const float* __restrict__ att_mat,
                 const float* __restrict__ W,     // W_bi[0]: [128,128]
                 const float* __restrict__ b_bi,
                 const int* __restrict__ t1_ctx,
                 const int* __restrict__ t2_ctx,
                 float* __restrict__ out) {
    extern __shared__ __align__(16) float sm[];
    float* sAM    = sm;                         // 64*128 (also producer scratch)
    float* sB     = sAM + K_CTX * D_DIM;        // 32*140
    float* rowsum = sB + M_HALF * SB_STRIDE;    // 64
    float* colsum = rowsum + K_CTX;             // 32 (this half's cols)
    float* rows_w = colsum + M_HALF;            // 64
    float* cols_w = rows_w + K_CTX;             // 64
    float* newA   = cols_w + K_CTX;             // 128 (also producer arow)
    float* newB   = newA + D_DIM;               // 128
    float* scal   = newB + D_DIM;               // 4
    __shared__ int sTick;

    const int bid  = blockIdx.x;
    const int c    = bid >> 1;
    const int h    = bid & 1;
    const int mb   = h * M_HALF;                // global m base of this half
    const int tid  = threadIdx.x;
    const int wid  = tid >> 5;                  // 0..15
    const int lane = tid & 31;

    // --- phase 1: zero shared accumulators ---
    if (tid < M_HALF) colsum[tid] = 0.f;
    if (tid < 4) scal[tid] = 0.f;

    // --- phase 2: producer — blocks 0..63 compute AM row = bid ---
    if (bid < K_CTX) {
        if (tid < D_DIM) {
            float a = table[(long long)t1_ctx[bid] * D_DIM + tid];
            newA[tid] = a;
            g_A[bid * D_DIM + tid] = a;
        }
        __syncthreads();
        {
            const int d = tid & 127;
            const int q = tid >> 7;
            const float* att = att_mat + (q * 32) * D_DIM + d;
            const float* ar  = newA + q * 32;
            float acc = 0.f;
#pragma unroll
            for (int e = 0; e < 32; e++)
                acc = fmaf(ar[e], att[e * D_DIM], acc);
            sAM[tid] = acc;   // scratch [4][128]
        }
        __syncthreads();
        if (tid < D_DIM) {
            g_AM[bid * D_DIM + tid] = sAM[tid] + sAM[D_DIM + tid]
                                    + sAM[2 * D_DIM + tid] + sAM[3 * D_DIM + tid];
            __threadfence();
        }
        __syncthreads();
        if (tid == 0) atomicAdd(&g_count, 1);
    } else {
        __syncthreads();
        __syncthreads();
    }

    // --- phase 3: gather this half's 32 B rows (float4, random table rows) ---
    const int* ctx = t2_ctx + c * K_CTX;
    {
        float4* sB4 = (float4*)sB;
#pragma unroll
        for (int i = tid; i < M_HALF * (D_DIM / 4); i += 512) {
            int m = i >> 5;                     // local row 0..31
            int v = i & 31;
            float4 b4 = __ldg((const float4*)(table + (long long)ctx[mb + m] * D_DIM) + v);
            sB4[m * SB_VEC + v] = b4;
        }
    }

    // --- phase 4: string cosine partials (cheap; every block, local only) ---
    {
        float pd = 0.f, p1 = 0.f, p2 = 0.f;
        if (tid < DS) {
            float x1 = str_t1[tid];
            float x2 = str_t2s[c * DS + tid];
            pd = x1 * x2; p1 = x1 * x1; p2 = x2 * x2;
        }
#pragma unroll
        for (int off = 16; off; off >>= 1) {
            pd += __shfl_down_sync(0xffffffffu, pd, off);
            p1 += __shfl_down_sync(0xffffffffu, p1, off);
            p2 += __shfl_down_sync(0xffffffffu, p2, off);
        }
        if (lane == 0 && wid < 7) {
            atomicAdd(&scal[0], pd);
            atomicAdd(&scal[1], p1);
            atomicAdd(&scal[2], p2);
        }
    }

    // --- phase 5: wait for all 64 AM rows, then stage AM to smem ---
    if (tid == 0) {
        while (((volatile int*)&g_count)[0] < K_CTX) {}
        __threadfence();
    }
    __syncthreads();
    {
        const float4* src = (const float4*)g_AM;
        float4* dst = (float4*)sAM;
#pragma unroll
        for (int i = tid; i < K_CTX * D_DIM / 4; i += 512)
            dst[i] = src[i];
    }
    __syncthreads();

    // --- phase 6: sim = tanh(AM @ B^T), warp w: k 4w..4w+3, lane: m=lane ---
    {
        const float4* amp = (const float4*)(sAM + wid * 4 * D_DIM);
        const float4* bp  = (const float4*)(sB + lane * SB_STRIDE);

        float acc0 = 0, acc1 = 0, acc2 = 0, acc3 = 0;
#pragma unroll 8
        for (int jv = 0; jv < D_DIM / 4; jv++) {
            float4 b = bp[jv];
            float4 a0 = amp[jv];
            float4 a1 = amp[32 + jv];
            float4 a2 = amp[64 + jv];
            float4 a3 = amp[96 + jv];
            acc0 = fmaf(a0.x, b.x, acc0); acc0 = fmaf(a0.y, b.y, acc0);
            acc0 = fmaf(a0.z, b.z, acc0); acc0 = fmaf(a0.w, b.w, acc0);
            acc1 = fmaf(a1.x, b.x, acc1); acc1 = fmaf(a1.y, b.y, acc1);
            acc1 = fmaf(a1.z, b.z, acc1); acc1 = fmaf(a1.w, b.w, acc1);
            acc2 = fmaf(a2.x, b.x, acc2); acc2 = fmaf(a2.y, b.y, acc2);
            acc2 = fmaf(a2.z, b.z, acc2); acc2 = fmaf(a2.w, b.w, acc2);
            acc3 = fmaf(a3.x, b.x, acc3); acc3 = fmaf(a3.y, b.y, acc3);
            acc3 = fmaf(a3.z, b.z, acc3); acc3 = fmaf(a3.w, b.w, acc3);
        }

        float s0 = tanhf(acc0), s1 = tanhf(acc1);
        float s2 = tanhf(acc2), s3 = tanhf(acc3);

        // rowsum partial over this half's 32 m: shfl reduce
        float r0 = s0, r1 = s1, r2 = s2, r3 = s3;
#pragma unroll
        for (int off = 16; off; off >>= 1) {
            r0 += __shfl_xor_sync(0xffffffffu, r0, off);
            r1 += __shfl_xor_sync(0xffffffffu, r1, off);
            r2 += __shfl_xor_sync(0xffffffffu, r2, off);
            r3 += __shfl_xor_sync(0xffffffffu, r3, off);
        }
        if (lane == 0) {
            rowsum[wid * 4 + 0] = r0;
            rowsum[wid * 4 + 1] = r1;
            rowsum[wid * 4 + 2] = r2;
            rowsum[wid * 4 + 3] = r3;
        }
        // colsum: complete over all 64 k once 16 warps add (this half's m)
        atomicAdd(&colsum[lane], s0 + s1 + s2 + s3);
    }
    __syncthreads();

    // --- phase 6b: publish partials; ticket decides tail owner ---
    if (tid < K_CTX) g_rowpart[c][h][tid] = rowsum[tid];
    if (tid < M_HALF) g_colsum[c][mb + tid] = colsum[tid];
    __syncthreads();
    if (tid == 0) {
        __threadfence();
        sTick = atomicAdd(&g_tick[c], 1);
    }
    __syncthreads();

    if (sTick == 1) {
        // ================= tail: only the last-arriving block =================
        if (tid == 0) __threadfence();
        __syncthreads();

        if (tid < K_CTX) {
            rowsum[tid] = g_rowpart[c][0][tid] + g_rowpart[c][1][tid];
            cols_w[tid] = g_colsum[c][tid];   // temp stash of full colsum
        }
        __syncthreads();

        // softmax over 64: warp 0 -> rows, warp 1 -> cols
        if (tid < 64) {
            const float* src = (tid < 32) ? rowsum : cols_w;
            float* dst       = (tid < 32) ? rows_w : cols_w;
            int l = tid & 31;
            float v0 = src[l]      * (1.f / 64.f);
            float v1 = src[l + 32] * (1.f / 64.f);
            float mx = fmaxf(v0, v1);
#pragma unroll
            for (int off = 16; off; off >>= 1)
                mx = fmaxf(mx, __shfl_xor_sync(0xffffffffu, mx, off));
            float e0 = __expf(v0 - mx);
            float e1 = __expf(v1 - mx);
            float s = e0 + e1;
#pragma unroll
            for (int off = 16; off; off >>= 1)
                s += __shfl_xor_sync(0xffffffffu, s, off);
            float inv = 1.f / s;
            dst[l]      = e0 * inv;
            dst[l + 32] = e1 * inv;
        }
        __syncthreads();

        // new_A from g_A (L2-hot); new_B: own half smem + other half re-gather
        if (tid < D_DIM) {
            float na = 0.f, nb = 0.f;
            const int ob = M_HALF - mb;        // other half's global m base
#pragma unroll 4
            for (int k = 0; k < K_CTX; k++)
                na = fmaf(rows_w[k], __ldg(g_A + k * D_DIM + tid), na);
#pragma unroll 4
            for (int m = 0; m < M_HALF; m++)
                nb = fmaf(cols_w[mb + m], sB[m * SB_STRIDE + tid], nb);
#pragma unroll 4
            for (int m = 0; m < M_HALF; m++)
                nb = fmaf(cols_w[ob + m],
                          __ldg(table + (long long)ctx[ob + m] * D_DIM + tid), nb);
            newA[tid] = na;
            newB[tid] = nb;
        }
        __syncthreads();

        // bilinear: con = newA @ W @ newB + b
        if (tid < D_DIM) {
            float s1 = 0.f;
#pragma unroll 4
            for (int d = 0; d < D_DIM; d++)
                s1 = fmaf(newA[d], W[d * D_DIM + tid], s1);
            float pc = s1 * newB[tid];
#pragma unroll
            for (int off = 16; off; off >>= 1)
                pc += __shfl_down_sync(0xffffffffu, pc, off);
            if (lane == 0) atomicAdd(&scal[3], pc);
        }
        __syncthreads();

        if (tid == 0) {
            float n1 = fmaxf(sqrtf(scal[1]), EPS);
            float n2 = fmaxf(sqrtf(scal[2]), EPS);
            float str_score = scal[0] / (n1 * n2);
            float con_score = scal[3] + b_bi[0];
            out[c] = 0.5f * str_score + 0.5f * con_score;
            g_tick[c] = 0;                     // reset for next replay
        }
    }

    // --- final: counter reset for graph replay (all blocks) ---
    if (tid == 0) {
        __threadfence();
        int d = atomicAdd(&g_done, 1);
        if (d == 2 * C_CAND - 1) {
            g_done  = 0;
            g_count = 0;
        }
    }
}

// ---------------------------------------------------------------------------
extern "C" void kernel_launch(void* const* d_in, const int* in_sizes, int n_in,
                              void* d_out, int out_size) {
    const float* table   = (const float*)d_in[0];
    const float* str_t1  = (const float*)d_in[1];
    const float* str_t2s = (const float*)d_in[2];
    const float* att_mat = (const float*)d_in[3];
    const float* W_bi    = (const float*)d_in[4];
    const float* b_bi    = (const float*)d_in[5];
    const int*   t1_ctx  = (const int*)d_in[6];
    const int*   t2_ctx  = (const int*)d_in[7];
    float* out = (float*)d_out;

    cudaFuncSetAttribute(cand_kernel,
                         cudaFuncAttributeMaxDynamicSharedMemorySize,
                         SMEM_FLOATS * sizeof(float));

    cand_kernel<<<2 * C_CAND, 512, SMEM_FLOATS * sizeof(float)>>>(
        table, str_t1, str_t2s, att_mat, W_bi, b_bi, t1_ctx, t2_ctx, out);
}

// round 7
// speedup vs baseline: 1.7756x; 1.7756x over previous
#include <cuda_runtime.h>
#include <math.h>
#include <stdint.h>

#define K_CTX 64
#define D_DIM 128
#define C_CAND 256
#define DS 200
#define EPS 1e-8f

// Scratch + sync (device globals; no allocation allowed)
__device__ __align__(16) float g_A[K_CTX * D_DIM];
__device__ __align__(16) float g_AM[K_CTX * D_DIM];
__device__ int g_count = 0;   // AM rows produced
__device__ int g_done  = 0;   // blocks finished (reset)

// sB row stride 140 floats (560B, 16B aligned): LDS.128 conflict-free
#define SB_STRIDE 140
#define SB_ROW_BYTES (SB_STRIDE * 4)   // 560
#define SMEM_FLOATS (8192 + K_CTX * SB_STRIDE + 4 * 64 + 2 * 128 + 4 + 4)

__device__ __forceinline__ uint32_t smem_u32(const void* p) {
    return (uint32_t)__cvta_generic_to_shared(p);
}
__device__ __forceinline__ void mbar_init(uint32_t mbar, uint32_t cnt) {
    asm volatile("mbarrier.init.shared.b64 [%0], %1;" :: "r"(mbar), "r"(cnt) : "memory");
}
__device__ __forceinline__ void mbar_expect_tx(uint32_t mbar, uint32_t bytes) {
    asm volatile("mbarrier.arrive.expect_tx.shared.b64 _, [%0], %1;"
                 :: "r"(mbar), "r"(bytes) : "memory");
}
__device__ __forceinline__ void mbar_wait(uint32_t mbar, uint32_t parity) {
    uint32_t done;
    asm volatile(
        "{\n\t.reg .pred p;\n\t"
        "mbarrier.try_wait.parity.acquire.cta.shared::cta.b64 p, [%1], %2;\n\t"
        "selp.b32 %0, 1, 0, p;\n\t}"
        : "=r"(done) : "r"(mbar), "r"(parity) : "memory");
    if (!done) {
        asm volatile(
            "{\n\t.reg .pred P1;\n\t"
            "WAIT_LOOP_%=:\n\t"
            "mbarrier.try_wait.parity.acquire.cta.shared::cta.b64 P1, [%0], %1, 0x989680;\n\t"
            "@P1 bra.uni WAIT_DONE_%=;\n\t"
            "bra.uni WAIT_LOOP_%=;\n\t"
            "WAIT_DONE_%=:\n\t}"
            :: "r"(mbar), "r"(parity) : "memory");
    }
}
__device__ __forceinline__ void bulk_g2s(uint32_t dst_smem, const void* src_gmem,
                                         uint32_t bytes, uint32_t mbar) {
    asm volatile(
        "cp.async.bulk.shared::cluster.global.mbarrier::complete_tx::bytes "
        "[%0], [%1], %2, [%3];"
        :: "r"(dst_smem), "l"(src_gmem), "r"(bytes), "r"(mbar) : "memory");
}

// ---------------------------------------------------------------------------
// Single fused kernel. grid = 256 (one block per candidate), block = 512.
// Blocks 0..63 additionally produce one AM row.
// ---------------------------------------------------------------------------
__global__ __launch_bounds__(512, 3)
void cand_kernel(const float* __restrict__ table,
                 const float* __restrict__ str_t1,
                 const float* __restrict__ str_t2s,
                 const float* __restrict__ att_mat,
                 const float* __restrict__ W,     // W_bi[0]: [128,128]
                 const float* __restrict__ b_bi,
                 const int* __restrict__ t1_ctx,
                 const int* __restrict__ t2_ctx,
                 float* __restrict__ out) {
    extern __shared__ __align__(16) float sm[];
    float* sAM    = sm;                        // 64*128 (producer/tail scratch too)
    float* sB     = sAM + K_CTX * D_DIM;       // 64*140
    float* rowsum = sB + K_CTX * SB_STRIDE;    // 64
    float* colsum = rowsum + K_CTX;            // 64
    float* rows_w = colsum + K_CTX;            // 64
    float* cols_w = rows_w + K_CTX;            // 64
    float* newA   = cols_w + K_CTX;            // 128 (producer arow)
    float* newB   = newA + D_DIM;              // 128
    float* scal   = newB + D_DIM;              // 4
    uint64_t* mbars = (uint64_t*)(scal + 4);   // [0]=gather, [1]=sAM stage

    const int c    = blockIdx.x;
    const int tid  = threadIdx.x;
    const int wid  = tid >> 5;                 // 0..15
    const int lane = tid & 31;
    const uint32_t mbar_g = smem_u32(&mbars[0]);
    const uint32_t mbar_a = smem_u32(&mbars[1]);

    // --- phase 0: init mbarriers + zero accumulators ---
    if (tid == 0) {
        mbar_init(mbar_g, 1);
        mbar_init(mbar_a, 1);
        mbar_expect_tx(mbar_g, K_CTX * D_DIM * 4);   // 32768 B of B rows
        mbar_expect_tx(mbar_a, K_CTX * D_DIM * 4);   // 32768 B of AM
    }
    if (tid < K_CTX) colsum[tid] = 0.f;
    if (tid < 4) scal[tid] = 0.f;
    __syncthreads();   // mbar init visible before any complete_tx can land

    // --- phase 1: kick off B-row gather via 64 bulk copies (512B each) ---
    const int* ctx = t2_ctx + c * K_CTX;
    if (tid < K_CTX) {
        bulk_g2s(smem_u32(sB) + tid * SB_ROW_BYTES,
                 table + (long long)ctx[tid] * D_DIM,
                 D_DIM * 4, mbar_g);
    }

    // --- phase 2: producer — blocks 0..63 compute AM row c (512 threads) ---
    if (c < K_CTX) {
        if (tid < D_DIM) {
            float a = table[(long long)t1_ctx[c] * D_DIM + tid];
            newA[tid] = a;
            g_A[c * D_DIM + tid] = a;
        }
        __syncthreads();
        {
            const int d = tid & 127;
            const int q = tid >> 7;
            const float* att = att_mat + (q * 32) * D_DIM + d;
            const float* ar  = newA + q * 32;
            float acc = 0.f;
#pragma unroll
            for (int e = 0; e < 32; e++)
                acc = fmaf(ar[e], att[e * D_DIM], acc);
            sAM[tid] = acc;   // scratch [4][128]
        }
        __syncthreads();
        if (tid < D_DIM) {
            g_AM[c * D_DIM + tid] = sAM[tid] + sAM[D_DIM + tid]
                                  + sAM[2 * D_DIM + tid] + sAM[3 * D_DIM + tid];
            __threadfence();
        }
        __syncthreads();
        if (tid == 0) atomicAdd(&g_count, 1);
    } else {
        __syncthreads();
        __syncthreads();
        __syncthreads();
    }

    // --- phase 3: string cosine partials (hides latency) ---
    {
        float pd = 0.f, p1 = 0.f, p2 = 0.f;
        if (tid < DS) {
            float x1 = str_t1[tid];
            float x2 = str_t2s[c * DS + tid];
            pd = x1 * x2; p1 = x1 * x1; p2 = x2 * x2;
        }
#pragma unroll
        for (int off = 16; off; off >>= 1) {
            pd += __shfl_down_sync(0xffffffffu, pd, off);
            p1 += __shfl_down_sync(0xffffffffu, p1, off);
            p2 += __shfl_down_sync(0xffffffffu, p2, off);
        }
        if (lane == 0 && wid < 7) {
            atomicAdd(&scal[0], pd);
            atomicAdd(&scal[1], p1);
            atomicAdd(&scal[2], p2);
        }
    }

    // --- phase 4: wait producers, then one 32KB bulk copy of AM ---
    if (tid == 0) {
        while (((volatile int*)&g_count)[0] < K_CTX) {}
        __threadfence();
        asm volatile("fence.proxy.async;" ::: "memory");
        bulk_g2s(smem_u32(sAM), g_AM, K_CTX * D_DIM * 4, mbar_a);
    }

    // --- phase 5: wait both bulk transfers, then block barrier ---
    mbar_wait(mbar_g, 0);
    mbar_wait(mbar_a, 0);
    __syncthreads();

    // --- phase 6: sim = tanh(AM @ B^T): warp w -> k 4w..4w+3; lane -> m l, l+32
    {
        const float4* am0 = (const float4*)(sAM + (wid * 4 + 0) * D_DIM);
        const float4* am1 = (const float4*)(sAM + (wid * 4 + 1) * D_DIM);
        const float4* am2 = (const float4*)(sAM + (wid * 4 + 2) * D_DIM);
        const float4* am3 = (const float4*)(sAM + (wid * 4 + 3) * D_DIM);
        const float4* b0p = (const float4*)(sB + lane * SB_STRIDE);
        const float4* b1p = (const float4*)(sB + (lane + 32) * SB_STRIDE);

        float acc00 = 0, acc01 = 0;
        float acc10 = 0, acc11 = 0;
        float acc20 = 0, acc21 = 0;
        float acc30 = 0, acc31 = 0;

#pragma unroll 4
        for (int jv = 0; jv < D_DIM / 4; jv++) {
            float4 a0 = am0[jv];
            float4 a1 = am1[jv];
            float4 a2 = am2[jv];
            float4 a3 = am3[jv];
            float4 b0 = b0p[jv];
            float4 b1 = b1p[jv];

            acc00 = fmaf(a0.x, b0.x, acc00); acc00 = fmaf(a0.y, b0.y, acc00);
            acc00 = fmaf(a0.z, b0.z, acc00); acc00 = fmaf(a0.w, b0.w, acc00);
            acc01 = fmaf(a0.x, b1.x, acc01); acc01 = fmaf(a0.y, b1.y, acc01);
            acc01 = fmaf(a0.z, b1.z, acc01); acc01 = fmaf(a0.w, b1.w, acc01);

            acc10 = fmaf(a1.x, b0.x, acc10); acc10 = fmaf(a1.y, b0.y, acc10);
            acc10 = fmaf(a1.z, b0.z, acc10); acc10 = fmaf(a1.w, b0.w, acc10);
            acc11 = fmaf(a1.x, b1.x, acc11); acc11 = fmaf(a1.y, b1.y, acc11);
            acc11 = fmaf(a1.z, b1.z, acc11); acc11 = fmaf(a1.w, b1.w, acc11);

            acc20 = fmaf(a2.x, b0.x, acc20); acc20 = fmaf(a2.y, b0.y, acc20);
            acc20 = fmaf(a2.z, b0.z, acc20); acc20 = fmaf(a2.w, b0.w, acc20);
            acc21 = fmaf(a2.x, b1.x, acc21); acc21 = fmaf(a2.y, b1.y, acc21);
            acc21 = fmaf(a2.z, b1.z, acc21); acc21 = fmaf(a2.w, b1.w, acc21);

            acc30 = fmaf(a3.x, b0.x, acc30); acc30 = fmaf(a3.y, b0.y, acc30);
            acc30 = fmaf(a3.z, b0.z, acc30); acc30 = fmaf(a3.w, b0.w, acc30);
            acc31 = fmaf(a3.x, b1.x, acc31); acc31 = fmaf(a3.y, b1.y, acc31);
            acc31 = fmaf(a3.z, b1.z, acc31); acc31 = fmaf(a3.w, b1.w, acc31);
        }

        float s00 = tanhf(acc00), s01 = tanhf(acc01);
        float s10 = tanhf(acc10), s11 = tanhf(acc11);
        float s20 = tanhf(acc20), s21 = tanhf(acc21);
        float s30 = tanhf(acc30), s31 = tanhf(acc31);

        float r0 = s00 + s01;
        float r1 = s10 + s11;
        float r2 = s20 + s21;
        float r3 = s30 + s31;
#pragma unroll
        for (int off = 16; off; off >>= 1) {
            r0 += __shfl_xor_sync(0xffffffffu, r0, off);
            r1 += __shfl_xor_sync(0xffffffffu, r1, off);
            r2 += __shfl_xor_sync(0xffffffffu, r2, off);
            r3 += __shfl_xor_sync(0xffffffffu, r3, off);
        }
        if (lane == 0) {
            rowsum[wid * 4 + 0] = r0;
            rowsum[wid * 4 + 1] = r1;
            rowsum[wid * 4 + 2] = r2;
            rowsum[wid * 4 + 3] = r3;
        }
        atomicAdd(&colsum[lane],      s00 + s10 + s20 + s30);
        atomicAdd(&colsum[lane + 32], s01 + s11 + s21 + s31);
    }
    __syncthreads();

    // --- phase 7: softmax over 64: warp 0 -> rows, warp 1 -> cols ---
    if (tid < 64) {
        const float* src = (tid < 32) ? rowsum : colsum;
        float* dst       = (tid < 32) ? rows_w : cols_w;
        int l = tid & 31;
        float v0 = src[l]      * (1.f / 64.f);
        float v1 = src[l + 32] * (1.f / 64.f);
        float mx = fmaxf(v0, v1);
#pragma unroll
        for (int off = 16; off; off >>= 1)
            mx = fmaxf(mx, __shfl_xor_sync(0xffffffffu, mx, off));
        float e0 = __expf(v0 - mx);
        float e1 = __expf(v1 - mx);
        float s = e0 + e1;
#pragma unroll
        for (int off = 16; off; off >>= 1)
            s += __shfl_xor_sync(0xffffffffu, s, off);
        float inv = 1.f / s;
        dst[l]      = e0 * inv;
        dst[l + 32] = e1 * inv;
    }
    __syncthreads();

    // --- phase 8: new_A / new_B with all 512 threads (4-way k partials) ---
    {
        const int d = tid & 127;
        const int q = tid >> 7;            // 0..3 -> k range [16q, 16q+16)
        float na = 0.f, nb = 0.f;
        const float* gA = g_A + (q * 16) * D_DIM + d;
        const float* sb = sB + (q * 16) * SB_STRIDE + d;
#pragma unroll
        for (int k = 0; k < 16; k++) {
            na = fmaf(rows_w[q * 16 + k], __ldg(gA + k * D_DIM), na);
            nb = fmaf(cols_w[q * 16 + k], sb[k * SB_STRIDE], nb);
        }
        sAM[tid]       = na;               // sAM free after sim: partial scratch
        sAM[512 + tid] = nb;
    }
    __syncthreads();
    if (tid < D_DIM) {
        newA[tid] = sAM[tid] + sAM[128 + tid] + sAM[256 + tid] + sAM[384 + tid];
        newB[tid] = sAM[512 + tid] + sAM[640 + tid] + sAM[768 + tid] + sAM[896 + tid];
    }
    __syncthreads();

    // --- phase 9: con = newA @ W @ newB + b (4-way d partials) ---
    {
        const int e = tid & 127;
        const int q = tid >> 7;            // d range [32q, 32q+32)
        const float* wp = W + (q * 32) * D_DIM + e;
        const float* ap = newA + q * 32;
        float s1 = 0.f;
#pragma unroll
        for (int d = 0; d < 32; d++)
            s1 = fmaf(ap[d], wp[d * D_DIM], s1);
        sAM[tid] = s1;
    }
    __syncthreads();
    if (tid < D_DIM) {
        float s1 = sAM[tid] + sAM[128 + tid] + sAM[256 + tid] + sAM[384 + tid];
        float pc = s1 * newB[tid];
#pragma unroll
        for (int off = 16; off; off >>= 1)
            pc += __shfl_down_sync(0xffffffffu, pc, off);
        if (lane == 0) atomicAdd(&scal[3], pc);
    }
    __syncthreads();

    if (tid == 0) {
        float n1 = fmaxf(sqrtf(scal[1]), EPS);
        float n2 = fmaxf(sqrtf(scal[2]), EPS);
        float str_score = scal[0] / (n1 * n2);
        float con_score = scal[3] + b_bi[0];
        out[c] = 0.5f * str_score + 0.5f * con_score;

        int d = atomicAdd(&g_done, 1);
        if (d == C_CAND - 1) {
            g_done  = 0;
            g_count = 0;
        }
    }
}

// ---------------------------------------------------------------------------
extern "C" void kernel_launch(void* const* d_in, const int* in_sizes, int n_in,
                              void* d_out, int out_size) {
    const float* table   = (const float*)d_in[0];
    const float* str_t1  = (const float*)d_in[1];
    const float* str_t2s = (const float*)d_in[2];
    const float* att_mat = (const float*)d_in[3];
    const float* W_bi    = (const float*)d_in[4];
    const float* b_bi    = (const float*)d_in[5];
    const int*   t1_ctx  = (const int*)d_in[6];
    const int*   t2_ctx  = (const int*)d_in[7];
    float* out = (float*)d_out;

    cudaFuncSetAttribute(cand_kernel,
                         cudaFuncAttributeMaxDynamicSharedMemorySize,
                         SMEM_FLOATS * sizeof(float));

    cand_kernel<<<C_CAND, 512, SMEM_FLOATS * sizeof(float)>>>(
        table, str_t1, str_t2s, att_mat, W_bi, b_bi, t1_ctx, t2_ctx, out);
}